// round 3
// baseline (speedup 1.0000x reference)
#include <cuda_runtime.h>
#include <cuda_bf16.h>

// TensorRepsTransform: per row n (N=65536, DIM=832)
//   out[0:64)         = t[0:64)                                   (order-0, even)
//   out[64+4s+j)      = sign(det L) * sum_k L[j][k] t[64+4s+k]    (order-1, odd), s in [0,64)
//   out[320+16s+4a+b) = sum_{k1,k2} L[a][k1] L[b][k2] t[320+16s+4k1+4k2]  (order-2, even)
//
// 64 threads (2 warps) per row: low register pressure -> high occupancy,
// all global accesses coalesced float4, order-2 rows exchanged inside
// 4-lane groups via width-4 shuffles.

#define ROW_DIM 832

__global__ __launch_bounds__(256) void trep_kernel(
    const float* __restrict__ tens,
    const float* __restrict__ lfr,
    float* __restrict__ out,
    int nrows)
{
    const int rowid = blockIdx.x * 4 + (threadIdx.x >> 6);
    const int l64   = threadIdx.x & 63;
    if (rowid >= nrows) return;

    const float* __restrict__ tr   = tens + (size_t)rowid * ROW_DIM;
    float* __restrict__       orow = out  + (size_t)rowid * ROW_DIM;

    // ---- front-batched loads ----
    // L: row-uniform address -> broadcast within each warp
    const float4* Lp = (const float4*)(lfr + (size_t)rowid * 16);
    float4 Lr0 = Lp[0], Lr1 = Lp[1], Lr2 = Lp[2], Lr3 = Lp[3];

    // order-0: 16 float4 (lanes 0..15 of warp 0)
    float4 q0;
    if (l64 < 16) q0 = __ldcs(((const float4*)tr) + l64);

    // order-1: 64 float4, one per thread (coalesced per warp)
    float4 v = __ldcs(((const float4*)(tr + 64)) + l64);

    // order-2: 128 float4, two per thread (coalesced per warp)
    float4 t0 = __ldcs(((const float4*)(tr + 320)) + l64);
    float4 t1 = __ldcs(((const float4*)(tr + 320)) + l64 + 64);

    // ---- det(L) sign ----
    float L00=Lr0.x, L01=Lr0.y, L02=Lr0.z, L03=Lr0.w;
    float L10=Lr1.x, L11=Lr1.y, L12=Lr1.z, L13=Lr1.w;
    float L20=Lr2.x, L21=Lr2.y, L22=Lr2.z, L23=Lr2.w;
    float L30=Lr3.x, L31=Lr3.y, L32=Lr3.z, L33=Lr3.w;

    float s0 = L00*L11 - L01*L10;
    float s1 = L00*L12 - L02*L10;
    float s2 = L00*L13 - L03*L10;
    float s3 = L01*L12 - L02*L11;
    float s4 = L01*L13 - L03*L11;
    float s5 = L02*L13 - L03*L12;
    float c5 = L22*L33 - L23*L32;
    float c4 = L21*L33 - L23*L31;
    float c3 = L21*L32 - L22*L31;
    float c2 = L20*L33 - L23*L30;
    float c1 = L20*L32 - L22*L30;
    float c0 = L20*L31 - L21*L30;
    float det = s0*c5 - s1*c4 + s2*c3 + s3*c2 - s4*c1 + s5*c0;
    float sgn = (det > 0.0f) ? 1.0f : ((det < 0.0f) ? -1.0f : 0.0f);

    // ---- order-0: passthrough ----
    if (l64 < 16) __stcs(((float4*)orow) + l64, q0);

    // ---- order-1: y = sgn * (L v), one slot per thread ----
    {
        float4 y;
        y.x = sgn * (L00*v.x + L01*v.y + L02*v.z + L03*v.w);
        y.y = sgn * (L10*v.x + L11*v.y + L12*v.z + L13*v.w);
        y.z = sgn * (L20*v.x + L21*v.y + L22*v.z + L23*v.w);
        y.w = sgn * (L30*v.x + L31*v.y + L32*v.z + L33*v.w);
        __stcs(((float4*)(orow + 64)) + l64, y);
    }

    // ---- order-2: U = L (T L^T), cooperative in 4-lane groups ----
    // float4 #g of the order-2 block is row (g&3) of slot (g>>2).
    // Within a warp, lanes 4k..4k+3 hold rows 0..3 of one slot for both
    // g = l64 and g = l64 + 64 (each contiguous per warp).
    const int r = l64 & 3;
    float4 Lrow = (r == 0) ? Lr0 : (r == 1) ? Lr1 : (r == 2) ? Lr2 : Lr3;

    #pragma unroll
    for (int a = 0; a < 2; a++) {
        float4 Ta = (a == 0) ? t0 : t1;

        // B[m] = sum_k L[m][k] * T[r][k]   (local)
        float4 B;
        B.x = L00*Ta.x + L01*Ta.y + L02*Ta.z + L03*Ta.w;
        B.y = L10*Ta.x + L11*Ta.y + L12*Ta.z + L13*Ta.w;
        B.z = L20*Ta.x + L21*Ta.y + L22*Ta.z + L23*Ta.w;
        B.w = L30*Ta.x + L31*Ta.y + L32*Ta.z + L33*Ta.w;

        // U[r][m] = sum_{r'} L[r][r'] * B_{r'}[m]   (width-4 shuffles)
        float4 U = make_float4(0.f, 0.f, 0.f, 0.f);
        #pragma unroll
        for (int rp = 0; rp < 4; rp++) {
            float bx = __shfl_sync(0xffffffffu, B.x, rp, 4);
            float by = __shfl_sync(0xffffffffu, B.y, rp, 4);
            float bz = __shfl_sync(0xffffffffu, B.z, rp, 4);
            float bw = __shfl_sync(0xffffffffu, B.w, rp, 4);
            float c = (rp == 0) ? Lrow.x : (rp == 1) ? Lrow.y
                    : (rp == 2) ? Lrow.z : Lrow.w;
            U.x += c * bx;
            U.y += c * by;
            U.z += c * bz;
            U.w += c * bw;
        }
        __stcs(((float4*)(orow + 320)) + 64 * a + l64, U);
    }
}

extern "C" void kernel_launch(void* const* d_in, const int* in_sizes, int n_in,
                              void* d_out, int out_size)
{
    const float* tens = (const float*)d_in[0];   // (N, 832) float32
    const float* lfr  = (const float*)d_in[1];   // (N, 4, 4) float32
    // d_in[2] = parity_odd mask: compile-time constant of REPS, folded into layout.
    (void)n_in; (void)out_size;

    int nrows = in_sizes[0] / ROW_DIM;           // 65536
    float* out = (float*)d_out;

    int nblocks = (nrows + 3) / 4;               // 4 rows per 256-thread block
    trep_kernel<<<nblocks, 256>>>(tens, lfr, out, nrows);
}

// round 4
// speedup vs baseline: 1.0117x; 1.0117x over previous
#include <cuda_runtime.h>
#include <cuda_bf16.h>

// TensorRepsTransform: per row n (N=65536, DIM=832)
//   out[0:64)         = t[0:64)                                   (order-0, even)
//   out[64+4s+j)      = sign(det L) * sum_k L[j][k] t[64+4s+k]    (order-1, odd), s in [0,64)
//   out[320+16s+4a+b) = sum_{k1,k2} L[a][k1] L[b][k2] t[320+16s+4k1+4k2]  (order-2, even)
//
// One warp per row (R2 structure: best measured). All global accesses are
// coalesced float4. Order-2 rows exchanged inside 4-lane groups via width-4
// shuffles. Changes vs R2: order-0 stored immediately (liveness trim) and
// __launch_bounds__(256,5) to target ~50 regs -> 5 blocks/SM.

#define ROW_DIM 832

__global__ __launch_bounds__(256, 5) void trep_kernel(
    const float* __restrict__ tens,
    const float* __restrict__ lfr,
    float* __restrict__ out,
    int nrows)
{
    const int gwarp = (int)((blockIdx.x * 256u + threadIdx.x) >> 5);
    const int lane  = threadIdx.x & 31;
    if (gwarp >= nrows) return;

    const float* __restrict__ tr   = tens + (size_t)gwarp * ROW_DIM;
    float* __restrict__       orow = out  + (size_t)gwarp * ROW_DIM;

    // ---- front-batched loads (max MLP) ----
    // order-2: 128 float4, 4 per lane (coalesced); longest-lived, issue first
    float4 t0 = __ldcs(((const float4*)(tr + 320)) + lane);
    float4 t1 = __ldcs(((const float4*)(tr + 320)) + lane + 32);
    float4 t2 = __ldcs(((const float4*)(tr + 320)) + lane + 64);
    float4 t3 = __ldcs(((const float4*)(tr + 320)) + lane + 96);

    // order-1: 64 float4, 2 per lane (coalesced)
    float4 v1 = __ldcs(((const float4*)(tr + 64)) + lane);
    float4 v2 = __ldcs(((const float4*)(tr + 64)) + lane + 32);

    // L: warp-uniform address -> broadcast
    const float4* Lp = (const float4*)(lfr + (size_t)gwarp * 16);
    float4 Lr0 = Lp[0], Lr1 = Lp[1], Lr2 = Lp[2], Lr3 = Lp[3];

    // order-0: passthrough, consumed immediately (no long-lived register)
    if (lane < 16) {
        float4 q0 = __ldcs(((const float4*)tr) + lane);
        __stcs(((float4*)orow) + lane, q0);
    }

    float L00=Lr0.x, L01=Lr0.y, L02=Lr0.z, L03=Lr0.w;
    float L10=Lr1.x, L11=Lr1.y, L12=Lr1.z, L13=Lr1.w;
    float L20=Lr2.x, L21=Lr2.y, L22=Lr2.z, L23=Lr2.w;
    float L30=Lr3.x, L31=Lr3.y, L32=Lr3.z, L33=Lr3.w;

    // ---- det(L) sign ----
    float det =
          (L00*L11 - L01*L10) * (L22*L33 - L23*L32)
        - (L00*L12 - L02*L10) * (L21*L33 - L23*L31)
        + (L00*L13 - L03*L10) * (L21*L32 - L22*L31)
        + (L01*L12 - L02*L11) * (L20*L33 - L23*L30)
        - (L01*L13 - L03*L11) * (L20*L32 - L22*L30)
        + (L02*L13 - L03*L12) * (L20*L31 - L21*L30);
    float sgn = (det > 0.0f) ? 1.0f : ((det < 0.0f) ? -1.0f : 0.0f);

    // ---- order-1: y = sgn * (L v), 2 slots per lane ----
    {
        float4 y;
        y.x = sgn * (L00*v1.x + L01*v1.y + L02*v1.z + L03*v1.w);
        y.y = sgn * (L10*v1.x + L11*v1.y + L12*v1.z + L13*v1.w);
        y.z = sgn * (L20*v1.x + L21*v1.y + L22*v1.z + L23*v1.w);
        y.w = sgn * (L30*v1.x + L31*v1.y + L32*v1.z + L33*v1.w);
        __stcs(((float4*)(orow + 64)) + lane, y);

        y.x = sgn * (L00*v2.x + L01*v2.y + L02*v2.z + L03*v2.w);
        y.y = sgn * (L10*v2.x + L11*v2.y + L12*v2.z + L13*v2.w);
        y.z = sgn * (L20*v2.x + L21*v2.y + L22*v2.z + L23*v2.w);
        y.w = sgn * (L30*v2.x + L31*v2.y + L32*v2.z + L33*v2.w);
        __stcs(((float4*)(orow + 64)) + lane + 32, y);
    }

    // ---- order-2: U = L (T L^T), cooperative in 4-lane groups ----
    // float4 #g of the order-2 block is row (g&3) of slot (g>>2).
    const int r = lane & 3;
    float4 Lrow = (r == 0) ? Lr0 : (r == 1) ? Lr1 : (r == 2) ? Lr2 : Lr3;

    #pragma unroll
    for (int a = 0; a < 4; a++) {
        float4 Ta = (a == 0) ? t0 : (a == 1) ? t1 : (a == 2) ? t2 : t3;

        // B[m] = sum_k L[m][k] * T[r][k]   (local)
        float4 B;
        B.x = L00*Ta.x + L01*Ta.y + L02*Ta.z + L03*Ta.w;
        B.y = L10*Ta.x + L11*Ta.y + L12*Ta.z + L13*Ta.w;
        B.z = L20*Ta.x + L21*Ta.y + L22*Ta.z + L23*Ta.w;
        B.w = L30*Ta.x + L31*Ta.y + L32*Ta.z + L33*Ta.w;

        // U[r][m] = sum_{r'} L[r][r'] * B_{r'}[m]   (width-4 shuffles)
        float4 U = make_float4(0.f, 0.f, 0.f, 0.f);
        #pragma unroll
        for (int rp = 0; rp < 4; rp++) {
            float bx = __shfl_sync(0xffffffffu, B.x, rp, 4);
            float by = __shfl_sync(0xffffffffu, B.y, rp, 4);
            float bz = __shfl_sync(0xffffffffu, B.z, rp, 4);
            float bw = __shfl_sync(0xffffffffu, B.w, rp, 4);
            float c = (rp == 0) ? Lrow.x : (rp == 1) ? Lrow.y
                    : (rp == 2) ? Lrow.z : Lrow.w;
            U.x += c * bx;
            U.y += c * by;
            U.z += c * bz;
            U.w += c * bw;
        }
        __stcs(((float4*)(orow + 320)) + 32 * a + lane, U);
    }
}

extern "C" void kernel_launch(void* const* d_in, const int* in_sizes, int n_in,
                              void* d_out, int out_size)
{
    const float* tens = (const float*)d_in[0];   // (N, 832) float32
    const float* lfr  = (const float*)d_in[1];   // (N, 4, 4) float32
    // d_in[2] = parity_odd mask: compile-time constant of REPS, folded into layout.
    (void)n_in; (void)out_size;

    int nrows = in_sizes[0] / ROW_DIM;           // 65536
    float* out = (float*)d_out;

    int nblocks = (nrows * 32 + 255) / 256;      // one warp per row
    trep_kernel<<<nblocks, 256>>>(tens, lfr, out, nrows);
}

// round 5
// speedup vs baseline: 1.0294x; 1.0175x over previous
#include <cuda_runtime.h>
#include <cuda_bf16.h>

// TensorRepsTransform: per row n (N=65536, DIM=832)
//   out[0:64)         = t[0:64)                                   (order-0, even)
//   out[64+4s+j)      = sign(det L) * sum_k L[j][k] t[64+4s+k]    (order-1, odd)
//   out[320+16s+4a+b) = sum_{k1,k2} L[a][k1] L[b][k2] t[320+16s+4k1+4k2]  (order-2, even)
//
// TWO rows per warp, all ~16 loads front-batched (max per-warp MLP, the
// measured lever for DRAM%). No register cap — R4 showed capping regs makes
// ptxas break the front batch. All accesses coalesced float4; order-2 rows
// exchanged in 4-lane groups via width-4 shuffles.

#define ROW_DIM 832

__device__ __forceinline__ float det_sign(
    float L00,float L01,float L02,float L03,
    float L10,float L11,float L12,float L13,
    float L20,float L21,float L22,float L23,
    float L30,float L31,float L32,float L33)
{
    float det =
          (L00*L11 - L01*L10) * (L22*L33 - L23*L32)
        - (L00*L12 - L02*L10) * (L21*L33 - L23*L31)
        + (L00*L13 - L03*L10) * (L21*L32 - L22*L31)
        + (L01*L12 - L02*L11) * (L20*L33 - L23*L30)
        - (L01*L13 - L03*L11) * (L20*L32 - L22*L30)
        + (L02*L13 - L03*L12) * (L20*L31 - L21*L30);
    return (det > 0.0f) ? 1.0f : ((det < 0.0f) ? -1.0f : 0.0f);
}

__device__ __forceinline__ void do_row(
    float* __restrict__ orow, int lane,
    float4 Lr0, float4 Lr1, float4 Lr2, float4 Lr3,
    float4 v1, float4 v2,
    float4 t0, float4 t1, float4 t2, float4 t3)
{
    float L00=Lr0.x, L01=Lr0.y, L02=Lr0.z, L03=Lr0.w;
    float L10=Lr1.x, L11=Lr1.y, L12=Lr1.z, L13=Lr1.w;
    float L20=Lr2.x, L21=Lr2.y, L22=Lr2.z, L23=Lr2.w;
    float L30=Lr3.x, L31=Lr3.y, L32=Lr3.z, L33=Lr3.w;

    float sgn = det_sign(L00,L01,L02,L03,L10,L11,L12,L13,
                         L20,L21,L22,L23,L30,L31,L32,L33);

    // order-1: y = sgn * (L v), 2 slots per lane
    float4 y;
    y.x = sgn * (L00*v1.x + L01*v1.y + L02*v1.z + L03*v1.w);
    y.y = sgn * (L10*v1.x + L11*v1.y + L12*v1.z + L13*v1.w);
    y.z = sgn * (L20*v1.x + L21*v1.y + L22*v1.z + L23*v1.w);
    y.w = sgn * (L30*v1.x + L31*v1.y + L32*v1.z + L33*v1.w);
    __stcs(((float4*)(orow + 64)) + lane, y);

    y.x = sgn * (L00*v2.x + L01*v2.y + L02*v2.z + L03*v2.w);
    y.y = sgn * (L10*v2.x + L11*v2.y + L12*v2.z + L13*v2.w);
    y.z = sgn * (L20*v2.x + L21*v2.y + L22*v2.z + L23*v2.w);
    y.w = sgn * (L30*v2.x + L31*v2.y + L32*v2.z + L33*v2.w);
    __stcs(((float4*)(orow + 64)) + lane + 32, y);

    // order-2: U = L (T L^T), cooperative in 4-lane groups
    const int r = lane & 3;
    float4 Lrow = (r == 0) ? Lr0 : (r == 1) ? Lr1 : (r == 2) ? Lr2 : Lr3;

    #pragma unroll
    for (int a = 0; a < 4; a++) {
        float4 Ta = (a == 0) ? t0 : (a == 1) ? t1 : (a == 2) ? t2 : t3;

        float4 B;
        B.x = L00*Ta.x + L01*Ta.y + L02*Ta.z + L03*Ta.w;
        B.y = L10*Ta.x + L11*Ta.y + L12*Ta.z + L13*Ta.w;
        B.z = L20*Ta.x + L21*Ta.y + L22*Ta.z + L23*Ta.w;
        B.w = L30*Ta.x + L31*Ta.y + L32*Ta.z + L33*Ta.w;

        float4 U = make_float4(0.f, 0.f, 0.f, 0.f);
        #pragma unroll
        for (int rp = 0; rp < 4; rp++) {
            float bx = __shfl_sync(0xffffffffu, B.x, rp, 4);
            float by = __shfl_sync(0xffffffffu, B.y, rp, 4);
            float bz = __shfl_sync(0xffffffffu, B.z, rp, 4);
            float bw = __shfl_sync(0xffffffffu, B.w, rp, 4);
            float c = (rp == 0) ? Lrow.x : (rp == 1) ? Lrow.y
                    : (rp == 2) ? Lrow.z : Lrow.w;
            U.x += c * bx;
            U.y += c * by;
            U.z += c * bz;
            U.w += c * bw;
        }
        __stcs(((float4*)(orow + 320)) + 32 * a + lane, U);
    }
}

__global__ __launch_bounds__(256) void trep_kernel(
    const float* __restrict__ tens,
    const float* __restrict__ lfr,
    float* __restrict__ out,
    int nhalf)   // nrows/2
{
    const int gwarp = (int)((blockIdx.x * 256u + threadIdx.x) >> 5);
    const int lane  = threadIdx.x & 31;
    if (gwarp >= nhalf) return;

    const int rA = gwarp;
    const int rB = gwarp + nhalf;

    const float* __restrict__ trA = tens + (size_t)rA * ROW_DIM;
    const float* __restrict__ trB = tens + (size_t)rB * ROW_DIM;
    float* __restrict__ oA = out + (size_t)rA * ROW_DIM;
    float* __restrict__ oB = out + (size_t)rB * ROW_DIM;

    // ================= front-batched loads for BOTH rows =================
    // order-2 (longest dependency chain first)
    float4 tA0 = __ldcs(((const float4*)(trA + 320)) + lane);
    float4 tA1 = __ldcs(((const float4*)(trA + 320)) + lane + 32);
    float4 tA2 = __ldcs(((const float4*)(trA + 320)) + lane + 64);
    float4 tA3 = __ldcs(((const float4*)(trA + 320)) + lane + 96);
    float4 tB0 = __ldcs(((const float4*)(trB + 320)) + lane);
    float4 tB1 = __ldcs(((const float4*)(trB + 320)) + lane + 32);
    float4 tB2 = __ldcs(((const float4*)(trB + 320)) + lane + 64);
    float4 tB3 = __ldcs(((const float4*)(trB + 320)) + lane + 96);

    // order-1
    float4 vA1 = __ldcs(((const float4*)(trA + 64)) + lane);
    float4 vA2 = __ldcs(((const float4*)(trA + 64)) + lane + 32);
    float4 vB1 = __ldcs(((const float4*)(trB + 64)) + lane);
    float4 vB2 = __ldcs(((const float4*)(trB + 64)) + lane + 32);

    // L matrices (warp-uniform -> broadcast)
    const float4* LpA = (const float4*)(lfr + (size_t)rA * 16);
    const float4* LpB = (const float4*)(lfr + (size_t)rB * 16);
    float4 LA0 = LpA[0], LA1 = LpA[1], LA2 = LpA[2], LA3 = LpA[3];
    float4 LB0 = LpB[0], LB1 = LpB[1], LB2 = LpB[2], LB3 = LpB[3];

    // order-0 passthrough (load + immediate store; short-lived regs)
    if (lane < 16) {
        float4 qA = __ldcs(((const float4*)trA) + lane);
        float4 qB = __ldcs(((const float4*)trB) + lane);
        __stcs(((float4*)oA) + lane, qA);
        __stcs(((float4*)oB) + lane, qB);
    }

    // ================= compute + store, row A then row B =================
    do_row(oA, lane, LA0, LA1, LA2, LA3, vA1, vA2, tA0, tA1, tA2, tA3);
    do_row(oB, lane, LB0, LB1, LB2, LB3, vB1, vB2, tB0, tB1, tB2, tB3);
}

extern "C" void kernel_launch(void* const* d_in, const int* in_sizes, int n_in,
                              void* d_out, int out_size)
{
    const float* tens = (const float*)d_in[0];   // (N, 832) float32
    const float* lfr  = (const float*)d_in[1];   // (N, 4, 4) float32
    // d_in[2] = parity_odd mask: compile-time constant of REPS, folded into layout.
    (void)n_in; (void)out_size;

    int nrows = in_sizes[0] / ROW_DIM;           // 65536
    int nhalf = nrows >> 1;                      // 2 rows per warp
    float* out = (float*)d_out;

    int nblocks = (nhalf * 32 + 255) / 256;
    trep_kernel<<<nblocks, 256>>>(tens, lfr, out, nhalf);
}